// round 8
// baseline (speedup 1.0000x reference)
#include <cuda_runtime.h>
#include <math_constants.h>
#include <float.h>

// Problem constants (fixed by the dataset instance)
#define B_ 4
#define S_ 1024
#define D_ 1024
#define H_ 16
#define HD 64

// Scratch (allocation-free rule: __device__ globals)
__device__ float g_qkv[B_ * S_ * 3 * D_];   // [B*S, 3D]
__device__ float g_ctx[B_ * S_ * D_];       // [B*S, D]

// Raw MUFU.EX2 (2^x). Softmax is computed in the log2 domain so this is the
// only transcendental needed (no companion FMUL as in __expf).
__device__ __forceinline__ float ex2f(float x) {
    float y;
    asm("ex2.approx.ftz.f32 %0, %1;" : "=f"(y) : "f"(x));
    return y;
}

// ---------------------------------------------------------------------------
// Tiled SGEMM with bias: C[M,N] = A[M,K] @ W[K,N] + bias[N]
// BM=BN=128, BK=16, 256 threads, 8x8 microtile (4+4 split halves).
// Double-buffered smem; next tile prefetched into registers before the FMA
// loop so LDG latency hides under 256 FFMA cycles; one syncthreads/iter.
// ---------------------------------------------------------------------------
#define GBM 128
#define GBN 128
#define GBK 16

__global__ __launch_bounds__(256, 2) void gemm_bias_kernel(
    const float* __restrict__ A, const float* __restrict__ W,
    const float* __restrict__ bias, float* __restrict__ C,
    int M, int N, int K)
{
    __shared__ float As[2][GBK * GBM];   // [k][m], stride 128
    __shared__ float Bs[2][GBK * GBN];   // [k][n], stride 128

    const int tid = threadIdx.x;
    const int tx = tid & 15;
    const int ty = tid >> 4;
    const int m0 = blockIdx.y * GBM;
    const int n0 = blockIdx.x * GBN;
    const int ry = ty << 2;              // row base, +64 for 2nd half
    const int cx = tx << 2;              // col base, +64 for 2nd half

    // A tile: 128 rows x 16 k -> 512 float4; thread handles e = tid, tid+256
    const int ar0 = tid >> 2,           ak0 = (tid & 3) << 2;
    const int ar1 = (tid + 256) >> 2,   ak1 = ((tid + 256) & 3) << 2;
    // B tile: 16 k x 128 n -> 512 float4; e>>5 = k row, (e&31)<<2 = n col
    const int br0 = tid >> 5,           bc0 = (tid & 31) << 2;
    const int br1 = (tid + 256) >> 5,   bc1 = ((tid + 256) & 31) << 2;

    float acc[8][8];
    #pragma unroll
    for (int i = 0; i < 8; i++)
        #pragma unroll
        for (int j = 0; j < 8; j++) acc[i][j] = 0.f;

    const int ntiles = K / GBK;

    auto load_regs = [&](int k0, float4& a0, float4& a1, float4& b0, float4& b1) {
        a0 = *(const float4*)(A + (size_t)(m0 + ar0) * K + k0 + ak0);
        a1 = *(const float4*)(A + (size_t)(m0 + ar1) * K + k0 + ak1);
        b0 = *(const float4*)(W + (size_t)(k0 + br0) * N + n0 + bc0);
        b1 = *(const float4*)(W + (size_t)(k0 + br1) * N + n0 + bc1);
    };
    auto store_smem = [&](int buf, const float4& a0, const float4& a1,
                          const float4& b0, const float4& b1) {
        As[buf][(ak0 + 0) * GBM + ar0] = a0.x;
        As[buf][(ak0 + 1) * GBM + ar0] = a0.y;
        As[buf][(ak0 + 2) * GBM + ar0] = a0.z;
        As[buf][(ak0 + 3) * GBM + ar0] = a0.w;
        As[buf][(ak1 + 0) * GBM + ar1] = a1.x;
        As[buf][(ak1 + 1) * GBM + ar1] = a1.y;
        As[buf][(ak1 + 2) * GBM + ar1] = a1.z;
        As[buf][(ak1 + 3) * GBM + ar1] = a1.w;
        *(float4*)&Bs[buf][br0 * GBN + bc0] = b0;
        *(float4*)&Bs[buf][br1 * GBN + bc1] = b1;
    };

    // Prologue: tile 0 -> smem buffer 0
    {
        float4 a0, a1, b0, b1;
        load_regs(0, a0, a1, b0, b1);
        store_smem(0, a0, a1, b0, b1);
    }
    __syncthreads();

    for (int t = 0; t < ntiles; t++) {
        const int buf = t & 1;
        float4 pa0, pa1, pb0, pb1;
        const bool more = (t + 1) < ntiles;
        if (more) load_regs((t + 1) * GBK, pa0, pa1, pb0, pb1);

        #pragma unroll
        for (int kk = 0; kk < GBK; kk++) {
            float4 a0 = *(float4*)&As[buf][kk * GBM + ry];
            float4 a1 = *(float4*)&As[buf][kk * GBM + ry + 64];
            float4 b0 = *(float4*)&Bs[buf][kk * GBN + cx];
            float4 b1 = *(float4*)&Bs[buf][kk * GBN + cx + 64];
            float av[8] = {a0.x, a0.y, a0.z, a0.w, a1.x, a1.y, a1.z, a1.w};
            float bv[8] = {b0.x, b0.y, b0.z, b0.w, b1.x, b1.y, b1.z, b1.w};
            #pragma unroll
            for (int i = 0; i < 8; i++)
                #pragma unroll
                for (int j = 0; j < 8; j++)
                    acc[i][j] += av[i] * bv[j];
        }

        if (more) store_smem(buf ^ 1, pa0, pa1, pb0, pb1);
        __syncthreads();
    }

    // Epilogue: bias + store
    float4 bv0 = *(const float4*)(bias + n0 + cx);
    float4 bv1 = *(const float4*)(bias + n0 + cx + 64);
    #pragma unroll
    for (int hm = 0; hm < 2; hm++) {
        #pragma unroll
        for (int ii = 0; ii < 4; ii++) {
            int i = hm * 4 + ii;
            int row = m0 + ry + hm * 64 + ii;
            float4 o0 = make_float4(acc[i][0] + bv0.x, acc[i][1] + bv0.y,
                                    acc[i][2] + bv0.z, acc[i][3] + bv0.w);
            float4 o1 = make_float4(acc[i][4] + bv1.x, acc[i][5] + bv1.y,
                                    acc[i][6] + bv1.z, acc[i][7] + bv1.w);
            *(float4*)(C + (size_t)row * N + n0 + cx)      = o0;
            *(float4*)(C + (size_t)row * N + n0 + cx + 64) = o1;
        }
    }
}

// ---------------------------------------------------------------------------
// Causal flash attention, log2-domain softmax. qkv layout [B*S, 3D]; head h
// uses cols h*64..h*64+63 of each Q/K/V third. One block = (q-tile, head, b).
// Heavy q-tiles launched FIRST (qt = 15 - bid.x) -> smaller ragged tail.
// 256 threads: rq = tid/16 owns rows 4rq..4rq+3; cq = tid%16 owns the 4-col
// score slice AND the 4-wide hd slice of the output.
// Scores carry a factor log2(e)/sqrt(hd) folded into Q, so p = 2^(s - m) via
// a single MUFU.EX2. Softmax reductions are phase-batched across the 4 rows
// so the four 26-cyc SHFL chains overlap instead of serializing.
// K/V tile loads batch all 8 LDGs before any STS (MLP=8).
// ---------------------------------------------------------------------------
#define AT 64
#define APAD 68
#define ATTN_SMEM ((2 * 64 * APAD + 64 * HD) * (int)sizeof(float))  // 51200 B
#define QSCALE 0.18033688011112042f   // (1/8) * log2(e)

__global__ __launch_bounds__(256) void attn_kernel(
    const float* __restrict__ qkv, float* __restrict__ ctx)
{
    extern __shared__ float sm[];
    float* sQt = sm;                    // [64][APAD] : [d][r], pre-scaled
    float* sKt = sm + 64 * APAD;        // [64][APAD] : [d][c]; reused as P[r][c]
    float* sV  = sm + 2 * 64 * APAD;    // [64][HD]   : [c][d]

    const int tid = threadIdx.x;
    const int qt = (int)gridDim.x - 1 - (int)blockIdx.x;  // heavy tiles first
    const int h  = blockIdx.y;
    const int b  = blockIdx.z;
    const int q0 = qt * AT;

    const int rq = tid >> 4;            // 0..15
    const int cq = tid & 15;            // 0..15

    const size_t rs = 3 * D_;           // qkv row stride
    const float* baseQ = qkv + (size_t)(b * S_) * rs + h * HD;
    const float* baseK = baseQ + D_;
    const float* baseV = baseQ + 2 * D_;

    // Per-thread K/V load coordinates: e = tid + 256*p, p=0..3
    int lc[4], ld4[4];
    #pragma unroll
    for (int p = 0; p < 4; p++) {
        int e = tid + (p << 8);
        lc[p]  = e >> 4;
        ld4[p] = (e & 15) << 2;
    }

    // Load Q tile transposed, folding in log2(e)/sqrt(hd)
    #pragma unroll
    for (int p = 0; p < 4; p++) {
        int r = lc[p], d4 = ld4[p];
        float4 q4 = *(const float4*)(baseQ + (size_t)(q0 + r) * rs + d4);
        sQt[(d4 + 0) * APAD + r] = QSCALE * q4.x;
        sQt[(d4 + 1) * APAD + r] = QSCALE * q4.y;
        sQt[(d4 + 2) * APAD + r] = QSCALE * q4.z;
        sQt[(d4 + 3) * APAD + r] = QSCALE * q4.w;
    }

    float m[4], l[4], o[4][4];
    #pragma unroll
    for (int i = 0; i < 4; i++) {
        m[i] = -CUDART_INF_F; l[i] = 0.f;
        #pragma unroll
        for (int j = 0; j < 4; j++) o[i][j] = 0.f;
    }

    for (int kt = 0; kt <= qt; kt++) {
        const int k0 = kt * AT;

        // Batch ALL global loads first (8 outstanding LDG.128 -> MLP=8)
        float4 kv4[4], vv4[4];
        #pragma unroll
        for (int p = 0; p < 4; p++) {
            const size_t roff = (size_t)(k0 + lc[p]) * rs + ld4[p];
            kv4[p] = *(const float4*)(baseK + roff);
            vv4[p] = *(const float4*)(baseV + roff);
        }

        __syncthreads();   // protect sKt(P)/sV still being read last iter
        #pragma unroll
        for (int p = 0; p < 4; p++) {
            int c = lc[p], d4 = ld4[p];
            sKt[(d4 + 0) * APAD + c] = kv4[p].x;
            sKt[(d4 + 1) * APAD + c] = kv4[p].y;
            sKt[(d4 + 2) * APAD + c] = kv4[p].z;
            sKt[(d4 + 3) * APAD + c] = kv4[p].w;
            *(float4*)&sV[c * HD + d4] = vv4[p];
        }
        __syncthreads();

        // Scores (log2 domain): 4x4 outer product per thread over d
        float acc[4][4];
        #pragma unroll
        for (int i = 0; i < 4; i++)
            #pragma unroll
            for (int j = 0; j < 4; j++) acc[i][j] = 0.f;

        #pragma unroll 8
        for (int d = 0; d < HD; d++) {
            float4 qa = *(float4*)&sQt[d * APAD + (rq << 2)];
            float4 kb = *(float4*)&sKt[d * APAD + (cq << 2)];
            float qv[4] = {qa.x, qa.y, qa.z, qa.w};
            float kv[4] = {kb.x, kb.y, kb.z, kb.w};
            #pragma unroll
            for (int i = 0; i < 4; i++)
                #pragma unroll
                for (int j = 0; j < 4; j++)
                    acc[i][j] += qv[i] * kv[j];
        }

        // Causal mask (only the diagonal tile is partial)
        if (kt == qt) {
            #pragma unroll
            for (int i = 0; i < 4; i++)
                #pragma unroll
                for (int j = 0; j < 4; j++)
                    if (k0 + (cq << 2) + j > q0 + (rq << 2) + i)
                        acc[i][j] = -FLT_MAX;
        }

        // Online softmax, log2 domain, PHASE-BATCHED across the 4 rows so the
        // four shuffle-reduction chains overlap (SHFL lat ~26 cyc each).
        float p[4][4], alpha[4], mnew[4], ssum[4];

        // Phase 1: local 4-way max per row
        #pragma unroll
        for (int i = 0; i < 4; i++)
            mnew[i] = fmaxf(fmaxf(acc[i][0], acc[i][1]),
                            fmaxf(acc[i][2], acc[i][3]));
        // Phase 2: 16-thread max reduction, all rows interleaved per step
        #pragma unroll
        for (int off = 8; off >= 1; off >>= 1) {
            #pragma unroll
            for (int i = 0; i < 4; i++)
                mnew[i] = fmaxf(mnew[i],
                                __shfl_xor_sync(0xffffffffu, mnew[i], off));
        }
        #pragma unroll
        for (int i = 0; i < 4; i++) mnew[i] = fmaxf(m[i], mnew[i]);

        // Phase 3: all 16 EX2s + local sums (independent, MUFU pipelined)
        #pragma unroll
        for (int i = 0; i < 4; i++) {
            p[i][0] = ex2f(acc[i][0] - mnew[i]);
            p[i][1] = ex2f(acc[i][1] - mnew[i]);
            p[i][2] = ex2f(acc[i][2] - mnew[i]);
            p[i][3] = ex2f(acc[i][3] - mnew[i]);
            ssum[i] = (p[i][0] + p[i][1]) + (p[i][2] + p[i][3]);
        }
        // Phase 4: 16-thread sum reduction, all rows interleaved per step
        #pragma unroll
        for (int off = 8; off >= 1; off >>= 1) {
            #pragma unroll
            for (int i = 0; i < 4; i++)
                ssum[i] += __shfl_xor_sync(0xffffffffu, ssum[i], off);
        }
        // Phase 5: state update
        #pragma unroll
        for (int i = 0; i < 4; i++) {
            alpha[i] = ex2f(m[i] - mnew[i]);
            m[i] = mnew[i];
            l[i] = l[i] * alpha[i] + ssum[i];
        }

        __syncthreads();   // everyone done reading sKt
        // Write P into the K buffer as [r][c], stride APAD
        #pragma unroll
        for (int i = 0; i < 4; i++)
            *(float4*)&sKt[((rq << 2) + i) * APAD + (cq << 2)] =
                make_float4(p[i][0], p[i][1], p[i][2], p[i][3]);
        // Rescale accumulated output
        #pragma unroll
        for (int i = 0; i < 4; i++)
            #pragma unroll
            for (int j = 0; j < 4; j++) o[i][j] *= alpha[i];
        __syncthreads();

        // O += P @ V. 4 key-columns per step: P via one LDS.128 per row
        // (2-address broadcast per warp), V via LDS.128.
        #pragma unroll 4
        for (int c4 = 0; c4 < AT; c4 += 4) {
            float4 pv[4];
            #pragma unroll
            for (int i = 0; i < 4; i++)
                pv[i] = *(float4*)&sKt[((rq << 2) + i) * APAD + c4];
            #pragma unroll
            for (int j = 0; j < 4; j++) {
                float4 vb = *(float4*)&sV[(c4 + j) * HD + (cq << 2)];
                float pj[4] = { ((const float*)&pv[0])[j],
                                ((const float*)&pv[1])[j],
                                ((const float*)&pv[2])[j],
                                ((const float*)&pv[3])[j] };
                #pragma unroll
                for (int i = 0; i < 4; i++) {
                    o[i][0] += pj[i] * vb.x;
                    o[i][1] += pj[i] * vb.y;
                    o[i][2] += pj[i] * vb.z;
                    o[i][3] += pj[i] * vb.w;
                }
            }
        }
    }

    // Final normalize + write ctx (merged-head layout [B*S, D])
    #pragma unroll
    for (int i = 0; i < 4; i++) {
        float inv = 1.f / l[i];
        float4 ov = make_float4(o[i][0] * inv, o[i][1] * inv,
                                o[i][2] * inv, o[i][3] * inv);
        *(float4*)(ctx + (size_t)(b * S_ + q0 + (rq << 2) + i) * D_
                   + h * HD + (cq << 2)) = ov;
    }
}

// ---------------------------------------------------------------------------
extern "C" void kernel_launch(void* const* d_in, const int* in_sizes, int n_in,
                              void* d_out, int out_size)
{
    const float* hs    = (const float*)d_in[0];   // [B,S,D]
    const float* att_w = (const float*)d_in[1];   // [D,3D]
    const float* att_b = (const float*)d_in[2];   // [3D]
    const float* out_w = (const float*)d_in[3];   // [D,D]
    const float* out_b = (const float*)d_in[4];   // [D]
    float* out = (float*)d_out;                   // [B,S,D]

    void *qkvp = nullptr, *ctxp = nullptr;
    cudaGetSymbolAddress(&qkvp, g_qkv);
    cudaGetSymbolAddress(&ctxp, g_ctx);

    // 1) QKV projection: [4096,1024] x [1024,3072] + bias
    gemm_bias_kernel<<<dim3(3 * D_ / GBN, B_ * S_ / GBM), 256>>>(
        hs, att_w, att_b, (float*)qkvp, B_ * S_, 3 * D_, D_);

    // 2) Causal flash attention per (q-tile, head, batch), heavy tiles first
    cudaFuncSetAttribute(attn_kernel,
                         cudaFuncAttributeMaxDynamicSharedMemorySize, ATTN_SMEM);
    attn_kernel<<<dim3(S_ / AT, H_, B_), 256, ATTN_SMEM>>>(
        (const float*)qkvp, (float*)ctxp);

    // 3) Output projection: [4096,1024] x [1024,1024] + bias
    gemm_bias_kernel<<<dim3(D_ / GBN, B_ * S_ / GBM), 256>>>(
        (const float*)ctxp, out_w, out_b, out, B_ * S_, D_, D_);
}

// round 11
// speedup vs baseline: 1.2586x; 1.2586x over previous
#include <cuda_runtime.h>
#include <math_constants.h>
#include <float.h>
#include <mma.h>

using namespace nvcuda;

// Problem constants (fixed by the dataset instance)
#define B_ 4
#define S_ 1024
#define D_ 1024
#define H_ 16
#define HD 64

// Scratch (allocation-free rule: __device__ globals)
__device__ float g_qkv[B_ * S_ * 3 * D_];   // [B*S, 3D]
__device__ float g_ctx[B_ * S_ * D_];       // [B*S, D]

// Raw MUFU.EX2 (2^x) for log2-domain softmax.
__device__ __forceinline__ float ex2f(float x) {
    float y;
    asm("ex2.approx.ftz.f32 %0, %1;" : "=f"(y) : "f"(x));
    return y;
}

// ---------------------------------------------------------------------------
// Bias prefill: C buffers are pre-loaded with the broadcast bias so the GEMM
// initializes its accumulators from C (layout-agnostic bias add).
// ---------------------------------------------------------------------------
#define QKV4 (B_ * S_ * 3 * D_ / 4)   // 3,145,728 float4
#define OUT4 (B_ * S_ * D_ / 4)       // 1,048,576 float4

__global__ void prefill_bias_kernel(float* __restrict__ qkv,
                                    const float* __restrict__ att_b,
                                    float* __restrict__ out,
                                    const float* __restrict__ out_b)
{
    const int idx = blockIdx.x * blockDim.x + threadIdx.x;
    if (idx < QKV4) {
        const int col4 = idx % (3 * D_ / 4);           // 768 cols of float4
        ((float4*)qkv)[idx] = ((const float4*)att_b)[col4];
    } else if (idx < QKV4 + OUT4) {
        const int j = idx - QKV4;
        const int col4 = j & (D_ / 4 - 1);             // 256 (pow2)
        ((float4*)out)[j] = ((const float4*)out_b)[col4];
    }
}

// ---------------------------------------------------------------------------
// TF32 tensor-core GEMM: C[M,N] += A[M,K] @ W[K,N] (C pre-filled with bias).
// BM=BN=128, BK=16, 256 threads = 8 warps in a 2x4 grid; each warp owns a
// 64x32 patch = 4x2 wmma m16n16k8 accumulators. Double-buffered smem with
// register prefetch (structure proven in the fp32 baseline).
// ---------------------------------------------------------------------------
#define TBM 128
#define TBN 128
#define TBK 16
#define LDA 20     // A smem row stride (pad 4): [m][k]
#define LDB 132    // B smem row stride (pad 4): [k][n]

__global__ __launch_bounds__(256, 2) void gemm_tf32_kernel(
    const float* __restrict__ A, const float* __restrict__ W,
    float* __restrict__ C, int M, int N, int K)
{
    __shared__ float As[2][TBM * LDA];
    __shared__ float Bs[2][TBK * LDB];

    const int tid = threadIdx.x;
    const int wid = tid >> 5;
    const int wm  = wid >> 2;            // 0..1 -> m offset 64*wm
    const int wn  = wid & 3;             // 0..3 -> n offset 32*wn
    const int m0 = blockIdx.y * TBM;
    const int n0 = blockIdx.x * TBN;

    // Per-thread tile-load coords (2 float4 each for A and B per tile)
    const int ar0 = tid >> 2,          ak0 = (tid & 3) << 2;
    const int ar1 = (tid + 256) >> 2,  ak1 = ((tid + 256) & 3) << 2;
    const int br0 = tid >> 5,          bc0 = (tid & 31) << 2;
    const int br1 = (tid + 256) >> 5,  bc1 = ((tid + 256) & 31) << 2;

    // Accumulators initialized from the bias-prefilled C
    wmma::fragment<wmma::accumulator, 16, 16, 8, float> acc[4][2];
    #pragma unroll
    for (int i = 0; i < 4; i++)
        #pragma unroll
        for (int j = 0; j < 2; j++)
            wmma::load_matrix_sync(acc[i][j],
                C + (size_t)(m0 + wm * 64 + i * 16) * N + n0 + wn * 32 + j * 16,
                N, wmma::mem_row_major);

    const int ntiles = K / TBK;

    auto load_regs = [&](int k0, float4& a0, float4& a1, float4& b0, float4& b1) {
        a0 = *(const float4*)(A + (size_t)(m0 + ar0) * K + k0 + ak0);
        a1 = *(const float4*)(A + (size_t)(m0 + ar1) * K + k0 + ak1);
        b0 = *(const float4*)(W + (size_t)(k0 + br0) * N + n0 + bc0);
        b1 = *(const float4*)(W + (size_t)(k0 + br1) * N + n0 + bc1);
    };
    auto store_smem = [&](int buf, const float4& a0, const float4& a1,
                          const float4& b0, const float4& b1) {
        *(float4*)&As[buf][ar0 * LDA + ak0] = a0;
        *(float4*)&As[buf][ar1 * LDA + ak1] = a1;
        *(float4*)&Bs[buf][br0 * LDB + bc0] = b0;
        *(float4*)&Bs[buf][br1 * LDB + bc1] = b1;
    };

    // Prologue: tile 0 -> buffer 0
    { float4 a0, a1, b0, b1; load_regs(0, a0, a1, b0, b1); store_smem(0, a0, a1, b0, b1); }
    __syncthreads();

    for (int t = 0; t < ntiles; t++) {
        const int buf = t & 1;
        float4 pa0, pa1, pb0, pb1;
        const bool more = (t + 1) < ntiles;
        if (more) load_regs((t + 1) * TBK, pa0, pa1, pb0, pb1);

        #pragma unroll
        for (int ks = 0; ks < 2; ks++) {
            const int k0 = ks * 8;
            wmma::fragment<wmma::matrix_a, 16, 16, 8, wmma::precision::tf32,
                           wmma::row_major> af[4];
            wmma::fragment<wmma::matrix_b, 16, 16, 8, wmma::precision::tf32,
                           wmma::row_major> bf[2];
            #pragma unroll
            for (int i = 0; i < 4; i++) {
                wmma::load_matrix_sync(af[i],
                    &As[buf][(wm * 64 + i * 16) * LDA + k0], LDA);
                #pragma unroll
                for (int e = 0; e < af[i].num_elements; e++)
                    af[i].x[e] = wmma::__float_to_tf32(af[i].x[e]);
            }
            #pragma unroll
            for (int j = 0; j < 2; j++) {
                wmma::load_matrix_sync(bf[j],
                    &Bs[buf][k0 * LDB + wn * 32 + j * 16], LDB);
                #pragma unroll
                for (int e = 0; e < bf[j].num_elements; e++)
                    bf[j].x[e] = wmma::__float_to_tf32(bf[j].x[e]);
            }
            #pragma unroll
            for (int i = 0; i < 4; i++)
                #pragma unroll
                for (int j = 0; j < 2; j++)
                    wmma::mma_sync(acc[i][j], af[i], bf[j], acc[i][j]);
        }

        if (more) store_smem(buf ^ 1, pa0, pa1, pb0, pb1);
        __syncthreads();
    }

    #pragma unroll
    for (int i = 0; i < 4; i++)
        #pragma unroll
        for (int j = 0; j < 2; j++)
            wmma::store_matrix_sync(
                C + (size_t)(m0 + wm * 64 + i * 16) * N + n0 + wn * 32 + j * 16,
                acc[i][j], N, wmma::mem_row_major);
}

// ---------------------------------------------------------------------------
// Causal flash attention, log2-domain softmax (UNCHANGED from the passing
// baseline). qkv layout [B*S, 3D]; head h uses cols h*64..h*64+63 of each
// Q/K/V third. Heavy q-tiles launched first; phase-batched softmax
// reductions; K/V loads batched to MLP=8; vectorized P@V.
// ---------------------------------------------------------------------------
#define AT 64
#define APAD 68
#define ATTN_SMEM ((2 * 64 * APAD + 64 * HD) * (int)sizeof(float))  // 51200 B
#define QSCALE 0.18033688011112042f   // (1/8) * log2(e)

__global__ __launch_bounds__(256) void attn_kernel(
    const float* __restrict__ qkv, float* __restrict__ ctx)
{
    extern __shared__ float sm[];
    float* sQt = sm;                    // [64][APAD] : [d][r], pre-scaled
    float* sKt = sm + 64 * APAD;        // [64][APAD] : [d][c]; reused as P[r][c]
    float* sV  = sm + 2 * 64 * APAD;    // [64][HD]   : [c][d]

    const int tid = threadIdx.x;
    const int qt = (int)gridDim.x - 1 - (int)blockIdx.x;  // heavy tiles first
    const int h  = blockIdx.y;
    const int b  = blockIdx.z;
    const int q0 = qt * AT;

    const int rq = tid >> 4;            // 0..15
    const int cq = tid & 15;            // 0..15

    const size_t rs = 3 * D_;           // qkv row stride
    const float* baseQ = qkv + (size_t)(b * S_) * rs + h * HD;
    const float* baseK = baseQ + D_;
    const float* baseV = baseQ + 2 * D_;

    // Per-thread K/V load coordinates: e = tid + 256*p, p=0..3
    int lc[4], ld4[4];
    #pragma unroll
    for (int p = 0; p < 4; p++) {
        int e = tid + (p << 8);
        lc[p]  = e >> 4;
        ld4[p] = (e & 15) << 2;
    }

    // Load Q tile transposed, folding in log2(e)/sqrt(hd)
    #pragma unroll
    for (int p = 0; p < 4; p++) {
        int r = lc[p], d4 = ld4[p];
        float4 q4 = *(const float4*)(baseQ + (size_t)(q0 + r) * rs + d4);
        sQt[(d4 + 0) * APAD + r] = QSCALE * q4.x;
        sQt[(d4 + 1) * APAD + r] = QSCALE * q4.y;
        sQt[(d4 + 2) * APAD + r] = QSCALE * q4.z;
        sQt[(d4 + 3) * APAD + r] = QSCALE * q4.w;
    }

    float m[4], l[4], o[4][4];
    #pragma unroll
    for (int i = 0; i < 4; i++) {
        m[i] = -CUDART_INF_F; l[i] = 0.f;
        #pragma unroll
        for (int j = 0; j < 4; j++) o[i][j] = 0.f;
    }

    for (int kt = 0; kt <= qt; kt++) {
        const int k0 = kt * AT;

        // Batch ALL global loads first (8 outstanding LDG.128 -> MLP=8)
        float4 kv4[4], vv4[4];
        #pragma unroll
        for (int p = 0; p < 4; p++) {
            const size_t roff = (size_t)(k0 + lc[p]) * rs + ld4[p];
            kv4[p] = *(const float4*)(baseK + roff);
            vv4[p] = *(const float4*)(baseV + roff);
        }

        __syncthreads();   // protect sKt(P)/sV still being read last iter
        #pragma unroll
        for (int p = 0; p < 4; p++) {
            int c = lc[p], d4 = ld4[p];
            sKt[(d4 + 0) * APAD + c] = kv4[p].x;
            sKt[(d4 + 1) * APAD + c] = kv4[p].y;
            sKt[(d4 + 2) * APAD + c] = kv4[p].z;
            sKt[(d4 + 3) * APAD + c] = kv4[p].w;
            *(float4*)&sV[c * HD + d4] = vv4[p];
        }
        __syncthreads();

        // Scores (log2 domain): 4x4 outer product per thread over d
        float acc[4][4];
        #pragma unroll
        for (int i = 0; i < 4; i++)
            #pragma unroll
            for (int j = 0; j < 4; j++) acc[i][j] = 0.f;

        #pragma unroll 8
        for (int d = 0; d < HD; d++) {
            float4 qa = *(float4*)&sQt[d * APAD + (rq << 2)];
            float4 kb = *(float4*)&sKt[d * APAD + (cq << 2)];
            float qv[4] = {qa.x, qa.y, qa.z, qa.w};
            float kv[4] = {kb.x, kb.y, kb.z, kb.w};
            #pragma unroll
            for (int i = 0; i < 4; i++)
                #pragma unroll
                for (int j = 0; j < 4; j++)
                    acc[i][j] += qv[i] * kv[j];
        }

        // Causal mask (only the diagonal tile is partial)
        if (kt == qt) {
            #pragma unroll
            for (int i = 0; i < 4; i++)
                #pragma unroll
                for (int j = 0; j < 4; j++)
                    if (k0 + (cq << 2) + j > q0 + (rq << 2) + i)
                        acc[i][j] = -FLT_MAX;
        }

        // Online softmax, log2 domain, phase-batched across the 4 rows
        float p[4][4], alpha[4], mnew[4], ssum[4];

        #pragma unroll
        for (int i = 0; i < 4; i++)
            mnew[i] = fmaxf(fmaxf(acc[i][0], acc[i][1]),
                            fmaxf(acc[i][2], acc[i][3]));
        #pragma unroll
        for (int off = 8; off >= 1; off >>= 1) {
            #pragma unroll
            for (int i = 0; i < 4; i++)
                mnew[i] = fmaxf(mnew[i],
                                __shfl_xor_sync(0xffffffffu, mnew[i], off));
        }
        #pragma unroll
        for (int i = 0; i < 4; i++) mnew[i] = fmaxf(m[i], mnew[i]);

        #pragma unroll
        for (int i = 0; i < 4; i++) {
            p[i][0] = ex2f(acc[i][0] - mnew[i]);
            p[i][1] = ex2f(acc[i][1] - mnew[i]);
            p[i][2] = ex2f(acc[i][2] - mnew[i]);
            p[i][3] = ex2f(acc[i][3] - mnew[i]);
            ssum[i] = (p[i][0] + p[i][1]) + (p[i][2] + p[i][3]);
        }
        #pragma unroll
        for (int off = 8; off >= 1; off >>= 1) {
            #pragma unroll
            for (int i = 0; i < 4; i++)
                ssum[i] += __shfl_xor_sync(0xffffffffu, ssum[i], off);
        }
        #pragma unroll
        for (int i = 0; i < 4; i++) {
            alpha[i] = ex2f(m[i] - mnew[i]);
            m[i] = mnew[i];
            l[i] = l[i] * alpha[i] + ssum[i];
        }

        __syncthreads();   // everyone done reading sKt
        #pragma unroll
        for (int i = 0; i < 4; i++)
            *(float4*)&sKt[((rq << 2) + i) * APAD + (cq << 2)] =
                make_float4(p[i][0], p[i][1], p[i][2], p[i][3]);
        #pragma unroll
        for (int i = 0; i < 4; i++)
            #pragma unroll
            for (int j = 0; j < 4; j++) o[i][j] *= alpha[i];
        __syncthreads();

        // O += P @ V. 4 key-columns per step, all-LDS.128.
        #pragma unroll 4
        for (int c4 = 0; c4 < AT; c4 += 4) {
            float4 pv[4];
            #pragma unroll
            for (int i = 0; i < 4; i++)
                pv[i] = *(float4*)&sKt[((rq << 2) + i) * APAD + c4];
            #pragma unroll
            for (int j = 0; j < 4; j++) {
                float4 vb = *(float4*)&sV[(c4 + j) * HD + (cq << 2)];
                float pj[4] = { ((const float*)&pv[0])[j],
                                ((const float*)&pv[1])[j],
                                ((const float*)&pv[2])[j],
                                ((const float*)&pv[3])[j] };
                #pragma unroll
                for (int i = 0; i < 4; i++) {
                    o[i][0] += pj[i] * vb.x;
                    o[i][1] += pj[i] * vb.y;
                    o[i][2] += pj[i] * vb.z;
                    o[i][3] += pj[i] * vb.w;
                }
            }
        }
    }

    // Final normalize + write ctx (merged-head layout [B*S, D])
    #pragma unroll
    for (int i = 0; i < 4; i++) {
        float inv = 1.f / l[i];
        float4 ov = make_float4(o[i][0] * inv, o[i][1] * inv,
                                o[i][2] * inv, o[i][3] * inv);
        *(float4*)(ctx + (size_t)(b * S_ + q0 + (rq << 2) + i) * D_
                   + h * HD + (cq << 2)) = ov;
    }
}

// ---------------------------------------------------------------------------
extern "C" void kernel_launch(void* const* d_in, const int* in_sizes, int n_in,
                              void* d_out, int out_size)
{
    const float* hs    = (const float*)d_in[0];   // [B,S,D]
    const float* att_w = (const float*)d_in[1];   // [D,3D]
    const float* att_b = (const float*)d_in[2];   // [3D]
    const float* out_w = (const float*)d_in[3];   // [D,D]
    const float* out_b = (const float*)d_in[4];   // [D]
    float* out = (float*)d_out;                   // [B,S,D]

    void *qkvp = nullptr, *ctxp = nullptr;
    cudaGetSymbolAddress(&qkvp, g_qkv);
    cudaGetSymbolAddress(&ctxp, g_ctx);

    // 0) Prefill C buffers with broadcast biases
    prefill_bias_kernel<<<(QKV4 + OUT4 + 255) / 256, 256>>>(
        (float*)qkvp, att_b, out, out_b);

    // 1) QKV projection (tf32 tensor cores): qkv += hs @ att_w
    gemm_tf32_kernel<<<dim3(3 * D_ / TBN, B_ * S_ / TBM), 256>>>(
        hs, att_w, (float*)qkvp, B_ * S_, 3 * D_, D_);

    // 2) Causal flash attention per (q-tile, head, batch), heavy tiles first
    cudaFuncSetAttribute(attn_kernel,
                         cudaFuncAttributeMaxDynamicSharedMemorySize, ATTN_SMEM);
    attn_kernel<<<dim3(S_ / AT, H_, B_), 256, ATTN_SMEM>>>(
        (const float*)qkvp, (float*)ctxp);

    // 3) Output projection (tf32 tensor cores): out += ctx @ out_w
    gemm_tf32_kernel<<<dim3(D_ / TBN, B_ * S_ / TBM), 256>>>(
        (const float*)ctxp, out_w, out, B_ * S_, D_, D_);
}

// round 14
// speedup vs baseline: 1.3166x; 1.0461x over previous
#include <cuda_runtime.h>
#include <math_constants.h>
#include <float.h>
#include <mma.h>

using namespace nvcuda;

// Problem constants (fixed by the dataset instance)
#define B_ 4
#define S_ 1024
#define D_ 1024
#define H_ 16
#define HD 64

// Scratch (allocation-free rule: __device__ globals)
__device__ float g_qkv[B_ * S_ * 3 * D_];   // [B*S, 3D]
__device__ float g_ctx[B_ * S_ * D_];       // [B*S, D]

// Raw MUFU.EX2 (2^x) for log2-domain softmax.
__device__ __forceinline__ float ex2f(float x) {
    float y;
    asm("ex2.approx.ftz.f32 %0, %1;" : "=f"(y) : "f"(x));
    return y;
}

// ---------------------------------------------------------------------------
// Bias prefill: C buffers are pre-loaded with the broadcast bias so the GEMM
// initializes its accumulators from C (layout-agnostic bias add).
// ---------------------------------------------------------------------------
#define QKV4 (B_ * S_ * 3 * D_ / 4)   // 3,145,728 float4
#define OUT4 (B_ * S_ * D_ / 4)       // 1,048,576 float4

__global__ void prefill_bias_kernel(float* __restrict__ qkv,
                                    const float* __restrict__ att_b,
                                    float* __restrict__ out,
                                    const float* __restrict__ out_b)
{
    const int idx = blockIdx.x * blockDim.x + threadIdx.x;
    if (idx < QKV4) {
        const int col4 = idx % (3 * D_ / 4);           // 768 cols of float4
        ((float4*)qkv)[idx] = ((const float4*)att_b)[col4];
    } else if (idx < QKV4 + OUT4) {
        const int j = idx - QKV4;
        const int col4 = j & (D_ / 4 - 1);             // 256 (pow2)
        ((float4*)out)[j] = ((const float4*)out_b)[col4];
    }
}

// ---------------------------------------------------------------------------
// TF32 tensor-core GEMM: C[M,N] += A[M,K] @ W[K,N] (C pre-filled with bias).
// BM=BN=128, BK=16, 256 threads = 8 warps in a 2x4 grid; each warp owns a
// 64x32 patch = 4x2 wmma m16n16k8 accumulators. Double-buffered smem with
// register prefetch. TF32 rounding is applied ONCE on the global->smem store
// path (off the critical path); fragments feed mma_sync directly with no
// per-element conversion chain between load and MMA.
// ---------------------------------------------------------------------------
#define TBM 128
#define TBN 128
#define TBK 16
#define LDA 20     // A smem row stride (pad 4): [m][k]
#define LDB 132    // B smem row stride (pad 4): [k][n]

__device__ __forceinline__ float4 cvt_tf32_f4(float4 v) {
    v.x = wmma::__float_to_tf32(v.x);
    v.y = wmma::__float_to_tf32(v.y);
    v.z = wmma::__float_to_tf32(v.z);
    v.w = wmma::__float_to_tf32(v.w);
    return v;
}

__global__ __launch_bounds__(256, 2) void gemm_tf32_kernel(
    const float* __restrict__ A, const float* __restrict__ W,
    float* __restrict__ C, int M, int N, int K)
{
    __shared__ float As[2][TBM * LDA];
    __shared__ float Bs[2][TBK * LDB];

    const int tid = threadIdx.x;
    const int wid = tid >> 5;
    const int wm  = wid >> 2;            // 0..1 -> m offset 64*wm
    const int wn  = wid & 3;             // 0..3 -> n offset 32*wn
    const int m0 = blockIdx.y * TBM;
    const int n0 = blockIdx.x * TBN;

    // Per-thread tile-load coords (2 float4 each for A and B per tile)
    const int ar0 = tid >> 2,          ak0 = (tid & 3) << 2;
    const int ar1 = (tid + 256) >> 2,  ak1 = ((tid + 256) & 3) << 2;
    const int br0 = tid >> 5,          bc0 = (tid & 31) << 2;
    const int br1 = (tid + 256) >> 5,  bc1 = ((tid + 256) & 31) << 2;

    // Accumulators initialized from the bias-prefilled C
    wmma::fragment<wmma::accumulator, 16, 16, 8, float> acc[4][2];
    #pragma unroll
    for (int i = 0; i < 4; i++)
        #pragma unroll
        for (int j = 0; j < 2; j++)
            wmma::load_matrix_sync(acc[i][j],
                C + (size_t)(m0 + wm * 64 + i * 16) * N + n0 + wn * 32 + j * 16,
                N, wmma::mem_row_major);

    const int ntiles = K / TBK;

    auto load_regs = [&](int k0, float4& a0, float4& a1, float4& b0, float4& b1) {
        a0 = *(const float4*)(A + (size_t)(m0 + ar0) * K + k0 + ak0);
        a1 = *(const float4*)(A + (size_t)(m0 + ar1) * K + k0 + ak1);
        b0 = *(const float4*)(W + (size_t)(k0 + br0) * N + n0 + bc0);
        b1 = *(const float4*)(W + (size_t)(k0 + br1) * N + n0 + bc1);
    };
    // tf32-round on the way into smem: fragments then need NO conversion.
    auto store_smem = [&](int buf, const float4& a0, const float4& a1,
                          const float4& b0, const float4& b1) {
        *(float4*)&As[buf][ar0 * LDA + ak0] = cvt_tf32_f4(a0);
        *(float4*)&As[buf][ar1 * LDA + ak1] = cvt_tf32_f4(a1);
        *(float4*)&Bs[buf][br0 * LDB + bc0] = cvt_tf32_f4(b0);
        *(float4*)&Bs[buf][br1 * LDB + bc1] = cvt_tf32_f4(b1);
    };

    // Prologue: tile 0 -> buffer 0
    { float4 a0, a1, b0, b1; load_regs(0, a0, a1, b0, b1); store_smem(0, a0, a1, b0, b1); }
    __syncthreads();

    for (int t = 0; t < ntiles; t++) {
        const int buf = t & 1;
        float4 pa0, pa1, pb0, pb1;
        const bool more = (t + 1) < ntiles;
        if (more) load_regs((t + 1) * TBK, pa0, pa1, pb0, pb1);

        #pragma unroll
        for (int ks = 0; ks < 2; ks++) {
            const int k0 = ks * 8;
            wmma::fragment<wmma::matrix_a, 16, 16, 8, wmma::precision::tf32,
                           wmma::row_major> af[4];
            wmma::fragment<wmma::matrix_b, 16, 16, 8, wmma::precision::tf32,
                           wmma::row_major> bf[2];
            #pragma unroll
            for (int i = 0; i < 4; i++)
                wmma::load_matrix_sync(af[i],
                    &As[buf][(wm * 64 + i * 16) * LDA + k0], LDA);
            #pragma unroll
            for (int j = 0; j < 2; j++)
                wmma::load_matrix_sync(bf[j],
                    &Bs[buf][k0 * LDB + wn * 32 + j * 16], LDB);
            #pragma unroll
            for (int i = 0; i < 4; i++)
                #pragma unroll
                for (int j = 0; j < 2; j++)
                    wmma::mma_sync(acc[i][j], af[i], bf[j], acc[i][j]);
        }

        if (more) store_smem(buf ^ 1, pa0, pa1, pb0, pb1);
        __syncthreads();
    }

    #pragma unroll
    for (int i = 0; i < 4; i++)
        #pragma unroll
        for (int j = 0; j < 2; j++)
            wmma::store_matrix_sync(
                C + (size_t)(m0 + wm * 64 + i * 16) * N + n0 + wn * 32 + j * 16,
                acc[i][j], N, wmma::mem_row_major);
}

// ---------------------------------------------------------------------------
// Causal flash attention, log2-domain softmax (UNCHANGED from the passing
// baseline). qkv layout [B*S, 3D]; head h uses cols h*64..h*64+63 of each
// Q/K/V third. Heavy q-tiles launched first; phase-batched softmax
// reductions; K/V loads batched to MLP=8; vectorized P@V.
// ---------------------------------------------------------------------------
#define AT 64
#define APAD 68
#define ATTN_SMEM ((2 * 64 * APAD + 64 * HD) * (int)sizeof(float))  // 51200 B
#define QSCALE 0.18033688011112042f   // (1/8) * log2(e)

__global__ __launch_bounds__(256) void attn_kernel(
    const float* __restrict__ qkv, float* __restrict__ ctx)
{
    extern __shared__ float sm[];
    float* sQt = sm;                    // [64][APAD] : [d][r], pre-scaled
    float* sKt = sm + 64 * APAD;        // [64][APAD] : [d][c]; reused as P[r][c]
    float* sV  = sm + 2 * 64 * APAD;    // [64][HD]   : [c][d]

    const int tid = threadIdx.x;
    const int qt = (int)gridDim.x - 1 - (int)blockIdx.x;  // heavy tiles first
    const int h  = blockIdx.y;
    const int b  = blockIdx.z;
    const int q0 = qt * AT;

    const int rq = tid >> 4;            // 0..15
    const int cq = tid & 15;            // 0..15

    const size_t rs = 3 * D_;           // qkv row stride
    const float* baseQ = qkv + (size_t)(b * S_) * rs + h * HD;
    const float* baseK = baseQ + D_;
    const float* baseV = baseQ + 2 * D_;

    // Per-thread K/V load coordinates: e = tid + 256*p, p=0..3
    int lc[4], ld4[4];
    #pragma unroll
    for (int p = 0; p < 4; p++) {
        int e = tid + (p << 8);
        lc[p]  = e >> 4;
        ld4[p] = (e & 15) << 2;
    }

    // Load Q tile transposed, folding in log2(e)/sqrt(hd)
    #pragma unroll
    for (int p = 0; p < 4; p++) {
        int r = lc[p], d4 = ld4[p];
        float4 q4 = *(const float4*)(baseQ + (size_t)(q0 + r) * rs + d4);
        sQt[(d4 + 0) * APAD + r] = QSCALE * q4.x;
        sQt[(d4 + 1) * APAD + r] = QSCALE * q4.y;
        sQt[(d4 + 2) * APAD + r] = QSCALE * q4.z;
        sQt[(d4 + 3) * APAD + r] = QSCALE * q4.w;
    }

    float m[4], l[4], o[4][4];
    #pragma unroll
    for (int i = 0; i < 4; i++) {
        m[i] = -CUDART_INF_F; l[i] = 0.f;
        #pragma unroll
        for (int j = 0; j < 4; j++) o[i][j] = 0.f;
    }

    for (int kt = 0; kt <= qt; kt++) {
        const int k0 = kt * AT;

        // Batch ALL global loads first (8 outstanding LDG.128 -> MLP=8)
        float4 kv4[4], vv4[4];
        #pragma unroll
        for (int p = 0; p < 4; p++) {
            const size_t roff = (size_t)(k0 + lc[p]) * rs + ld4[p];
            kv4[p] = *(const float4*)(baseK + roff);
            vv4[p] = *(const float4*)(baseV + roff);
        }

        __syncthreads();   // protect sKt(P)/sV still being read last iter
        #pragma unroll
        for (int p = 0; p < 4; p++) {
            int c = lc[p], d4 = ld4[p];
            sKt[(d4 + 0) * APAD + c] = kv4[p].x;
            sKt[(d4 + 1) * APAD + c] = kv4[p].y;
            sKt[(d4 + 2) * APAD + c] = kv4[p].z;
            sKt[(d4 + 3) * APAD + c] = kv4[p].w;
            *(float4*)&sV[c * HD + d4] = vv4[p];
        }
        __syncthreads();

        // Scores (log2 domain): 4x4 outer product per thread over d
        float acc[4][4];
        #pragma unroll
        for (int i = 0; i < 4; i++)
            #pragma unroll
            for (int j = 0; j < 4; j++) acc[i][j] = 0.f;

        #pragma unroll 8
        for (int d = 0; d < HD; d++) {
            float4 qa = *(float4*)&sQt[d * APAD + (rq << 2)];
            float4 kb = *(float4*)&sKt[d * APAD + (cq << 2)];
            float qv[4] = {qa.x, qa.y, qa.z, qa.w};
            float kv[4] = {kb.x, kb.y, kb.z, kb.w};
            #pragma unroll
            for (int i = 0; i < 4; i++)
                #pragma unroll
                for (int j = 0; j < 4; j++)
                    acc[i][j] += qv[i] * kv[j];
        }

        // Causal mask (only the diagonal tile is partial)
        if (kt == qt) {
            #pragma unroll
            for (int i = 0; i < 4; i++)
                #pragma unroll
                for (int j = 0; j < 4; j++)
                    if (k0 + (cq << 2) + j > q0 + (rq << 2) + i)
                        acc[i][j] = -FLT_MAX;
        }

        // Online softmax, log2 domain, phase-batched across the 4 rows
        float p[4][4], alpha[4], mnew[4], ssum[4];

        #pragma unroll
        for (int i = 0; i < 4; i++)
            mnew[i] = fmaxf(fmaxf(acc[i][0], acc[i][1]),
                            fmaxf(acc[i][2], acc[i][3]));
        #pragma unroll
        for (int off = 8; off >= 1; off >>= 1) {
            #pragma unroll
            for (int i = 0; i < 4; i++)
                mnew[i] = fmaxf(mnew[i],
                                __shfl_xor_sync(0xffffffffu, mnew[i], off));
        }
        #pragma unroll
        for (int i = 0; i < 4; i++) mnew[i] = fmaxf(m[i], mnew[i]);

        #pragma unroll
        for (int i = 0; i < 4; i++) {
            p[i][0] = ex2f(acc[i][0] - mnew[i]);
            p[i][1] = ex2f(acc[i][1] - mnew[i]);
            p[i][2] = ex2f(acc[i][2] - mnew[i]);
            p[i][3] = ex2f(acc[i][3] - mnew[i]);
            ssum[i] = (p[i][0] + p[i][1]) + (p[i][2] + p[i][3]);
        }
        #pragma unroll
        for (int off = 8; off >= 1; off >>= 1) {
            #pragma unroll
            for (int i = 0; i < 4; i++)
                ssum[i] += __shfl_xor_sync(0xffffffffu, ssum[i], off);
        }
        #pragma unroll
        for (int i = 0; i < 4; i++) {
            alpha[i] = ex2f(m[i] - mnew[i]);
            m[i] = mnew[i];
            l[i] = l[i] * alpha[i] + ssum[i];
        }

        __syncthreads();   // everyone done reading sKt
        #pragma unroll
        for (int i = 0; i < 4; i++)
            *(float4*)&sKt[((rq << 2) + i) * APAD + (cq << 2)] =
                make_float4(p[i][0], p[i][1], p[i][2], p[i][3]);
        #pragma unroll
        for (int i = 0; i < 4; i++)
            #pragma unroll
            for (int j = 0; j < 4; j++) o[i][j] *= alpha[i];
        __syncthreads();

        // O += P @ V. 4 key-columns per step, all-LDS.128.
        #pragma unroll 4
        for (int c4 = 0; c4 < AT; c4 += 4) {
            float4 pv[4];
            #pragma unroll
            for (int i = 0; i < 4; i++)
                pv[i] = *(float4*)&sKt[((rq << 2) + i) * APAD + c4];
            #pragma unroll
            for (int j = 0; j < 4; j++) {
                float4 vb = *(float4*)&sV[(c4 + j) * HD + (cq << 2)];
                float pj[4] = { ((const float*)&pv[0])[j],
                                ((const float*)&pv[1])[j],
                                ((const float*)&pv[2])[j],
                                ((const float*)&pv[3])[j] };
                #pragma unroll
                for (int i = 0; i < 4; i++) {
                    o[i][0] += pj[i] * vb.x;
                    o[i][1] += pj[i] * vb.y;
                    o[i][2] += pj[i] * vb.z;
                    o[i][3] += pj[i] * vb.w;
                }
            }
        }
    }

    // Final normalize + write ctx (merged-head layout [B*S, D])
    #pragma unroll
    for (int i = 0; i < 4; i++) {
        float inv = 1.f / l[i];
        float4 ov = make_float4(o[i][0] * inv, o[i][1] * inv,
                                o[i][2] * inv, o[i][3] * inv);
        *(float4*)(ctx + (size_t)(b * S_ + q0 + (rq << 2) + i) * D_
                   + h * HD + (cq << 2)) = ov;
    }
}

// ---------------------------------------------------------------------------
extern "C" void kernel_launch(void* const* d_in, const int* in_sizes, int n_in,
                              void* d_out, int out_size)
{
    const float* hs    = (const float*)d_in[0];   // [B,S,D]
    const float* att_w = (const float*)d_in[1];   // [D,3D]
    const float* att_b = (const float*)d_in[2];   // [3D]
    const float* out_w = (const float*)d_in[3];   // [D,D]
    const float* out_b = (const float*)d_in[4];   // [D]
    float* out = (float*)d_out;                   // [B,S,D]

    void *qkvp = nullptr, *ctxp = nullptr;
    cudaGetSymbolAddress(&qkvp, g_qkv);
    cudaGetSymbolAddress(&ctxp, g_ctx);

    // 0) Prefill C buffers with broadcast biases
    prefill_bias_kernel<<<(QKV4 + OUT4 + 255) / 256, 256>>>(
        (float*)qkvp, att_b, out, out_b);

    // 1) QKV projection (tf32 tensor cores): qkv += hs @ att_w
    gemm_tf32_kernel<<<dim3(3 * D_ / TBN, B_ * S_ / TBM), 256>>>(
        hs, att_w, (float*)qkvp, B_ * S_, 3 * D_, D_);

    // 2) Causal flash attention per (q-tile, head, batch), heavy tiles first
    cudaFuncSetAttribute(attn_kernel,
                         cudaFuncAttributeMaxDynamicSharedMemorySize, ATTN_SMEM);
    attn_kernel<<<dim3(S_ / AT, H_, B_), 256, ATTN_SMEM>>>(
        (const float*)qkvp, (float*)ctxp);

    // 3) Output projection (tf32 tensor cores): out += ctx @ out_w
    gemm_tf32_kernel<<<dim3(D_ / TBN, B_ * S_ / TBM), 256>>>(
        (const float*)ctxp, out_w, out, B_ * S_, D_, D_);
}

// round 17
// speedup vs baseline: 1.4881x; 1.1302x over previous
#include <cuda_runtime.h>
#include <math_constants.h>
#include <float.h>
#include <mma.h>

using namespace nvcuda;

// Problem constants (fixed by the dataset instance)
#define B_ 4
#define S_ 1024
#define D_ 1024
#define H_ 16
#define HD 64

// Scratch (allocation-free rule: __device__ globals)
__device__ float g_qkv[B_ * S_ * 3 * D_];   // [B*S, 3D]
__device__ float g_ctx[B_ * S_ * D_];       // [B*S, D]

// Raw MUFU.EX2 (2^x) for log2-domain softmax.
__device__ __forceinline__ float ex2f(float x) {
    float y;
    asm("ex2.approx.ftz.f32 %0, %1;" : "=f"(y) : "f"(x));
    return y;
}

// ---------------------------------------------------------------------------
// Bias prefill (unchanged, verified)
// ---------------------------------------------------------------------------
#define QKV4 (B_ * S_ * 3 * D_ / 4)
#define OUT4 (B_ * S_ * D_ / 4)

__global__ void prefill_bias_kernel(float* __restrict__ qkv,
                                    const float* __restrict__ att_b,
                                    float* __restrict__ out,
                                    const float* __restrict__ out_b)
{
    const int idx = blockIdx.x * blockDim.x + threadIdx.x;
    if (idx < QKV4) {
        const int col4 = idx % (3 * D_ / 4);
        ((float4*)qkv)[idx] = ((const float4*)att_b)[col4];
    } else if (idx < QKV4 + OUT4) {
        const int j = idx - QKV4;
        const int col4 = j & (D_ / 4 - 1);
        ((float4*)out)[j] = ((const float4*)out_b)[col4];
    }
}

// ---------------------------------------------------------------------------
// TF32 tensor-core GEMM (unchanged, verified at 881.8us total)
// ---------------------------------------------------------------------------
#define TBM 128
#define TBN 128
#define TBK 16
#define LDA 20
#define LDB 132

__device__ __forceinline__ float4 cvt_tf32_f4(float4 v) {
    v.x = wmma::__float_to_tf32(v.x);
    v.y = wmma::__float_to_tf32(v.y);
    v.z = wmma::__float_to_tf32(v.z);
    v.w = wmma::__float_to_tf32(v.w);
    return v;
}

__global__ __launch_bounds__(256, 2) void gemm_tf32_kernel(
    const float* __restrict__ A, const float* __restrict__ W,
    float* __restrict__ C, int M, int N, int K)
{
    __shared__ float As[2][TBM * LDA];
    __shared__ float Bs[2][TBK * LDB];

    const int tid = threadIdx.x;
    const int wid = tid >> 5;
    const int wm  = wid >> 2;
    const int wn  = wid & 3;
    const int m0 = blockIdx.y * TBM;
    const int n0 = blockIdx.x * TBN;

    const int ar0 = tid >> 2,          ak0 = (tid & 3) << 2;
    const int ar1 = (tid + 256) >> 2,  ak1 = ((tid + 256) & 3) << 2;
    const int br0 = tid >> 5,          bc0 = (tid & 31) << 2;
    const int br1 = (tid + 256) >> 5,  bc1 = ((tid + 256) & 31) << 2;

    wmma::fragment<wmma::accumulator, 16, 16, 8, float> acc[4][2];
    #pragma unroll
    for (int i = 0; i < 4; i++)
        #pragma unroll
        for (int j = 0; j < 2; j++)
            wmma::load_matrix_sync(acc[i][j],
                C + (size_t)(m0 + wm * 64 + i * 16) * N + n0 + wn * 32 + j * 16,
                N, wmma::mem_row_major);

    const int ntiles = K / TBK;

    auto load_regs = [&](int k0, float4& a0, float4& a1, float4& b0, float4& b1) {
        a0 = *(const float4*)(A + (size_t)(m0 + ar0) * K + k0 + ak0);
        a1 = *(const float4*)(A + (size_t)(m0 + ar1) * K + k0 + ak1);
        b0 = *(const float4*)(W + (size_t)(k0 + br0) * N + n0 + bc0);
        b1 = *(const float4*)(W + (size_t)(k0 + br1) * N + n0 + bc1);
    };
    auto store_smem = [&](int buf, const float4& a0, const float4& a1,
                          const float4& b0, const float4& b1) {
        *(float4*)&As[buf][ar0 * LDA + ak0] = cvt_tf32_f4(a0);
        *(float4*)&As[buf][ar1 * LDA + ak1] = cvt_tf32_f4(a1);
        *(float4*)&Bs[buf][br0 * LDB + bc0] = cvt_tf32_f4(b0);
        *(float4*)&Bs[buf][br1 * LDB + bc1] = cvt_tf32_f4(b1);
    };

    { float4 a0, a1, b0, b1; load_regs(0, a0, a1, b0, b1); store_smem(0, a0, a1, b0, b1); }
    __syncthreads();

    for (int t = 0; t < ntiles; t++) {
        const int buf = t & 1;
        float4 pa0, pa1, pb0, pb1;
        const bool more = (t + 1) < ntiles;
        if (more) load_regs((t + 1) * TBK, pa0, pa1, pb0, pb1);

        #pragma unroll
        for (int ks = 0; ks < 2; ks++) {
            const int k0 = ks * 8;
            wmma::fragment<wmma::matrix_a, 16, 16, 8, wmma::precision::tf32,
                           wmma::row_major> af[4];
            wmma::fragment<wmma::matrix_b, 16, 16, 8, wmma::precision::tf32,
                           wmma::row_major> bf[2];
            #pragma unroll
            for (int i = 0; i < 4; i++)
                wmma::load_matrix_sync(af[i],
                    &As[buf][(wm * 64 + i * 16) * LDA + k0], LDA);
            #pragma unroll
            for (int j = 0; j < 2; j++)
                wmma::load_matrix_sync(bf[j],
                    &Bs[buf][k0 * LDB + wn * 32 + j * 16], LDB);
            #pragma unroll
            for (int i = 0; i < 4; i++)
                #pragma unroll
                for (int j = 0; j < 2; j++)
                    wmma::mma_sync(acc[i][j], af[i], bf[j], acc[i][j]);
        }

        if (more) store_smem(buf ^ 1, pa0, pa1, pb0, pb1);
        __syncthreads();
    }

    #pragma unroll
    for (int i = 0; i < 4; i++)
        #pragma unroll
        for (int j = 0; j < 2; j++)
            wmma::store_matrix_sync(
                C + (size_t)(m0 + wm * 64 + i * 16) * N + n0 + wn * 32 + j * 16,
                acc[i][j], N, wmma::mem_row_major);
}

// ---------------------------------------------------------------------------
// Causal flash attention with TENSOR-CORE QK^T and P@V (tf32 wmma).
// Scalar online-softmax skeleton unchanged: scores go through smem
// (store_matrix_sync row-major, layout guaranteed), the 16x16-thread
// softmax reads/masks/ex2/reduces exactly as the verified baseline, writes
// P back to smem; PV result returns via smem for the per-row alpha-rescaled
// accumulation (fragment row mapping never needed).
// smem: sQ[64][72] [r][d] (pre-scaled), sK[64][72] [c][d], sV[64][72] [c][d],
//       sP[64][68] scores/P, sPV[64][68] PV tile.  90112 B total.
// ---------------------------------------------------------------------------
#define AT 64
#define KLD 72     // Q/K/V row stride (mult of 4)
#define PLD 68     // P/PV row stride (mult of 4)
#define SM_Q  0
#define SM_K  (64 * KLD)
#define SM_V  (2 * 64 * KLD)
#define SM_P  (3 * 64 * KLD)
#define SM_PV (3 * 64 * KLD + 64 * PLD)
#define ATTN_SMEM ((3 * 64 * KLD + 2 * 64 * PLD) * (int)sizeof(float))  // 90112
#define QSCALE 0.18033688011112042f   // (1/8) * log2(e)

__global__ __launch_bounds__(256) void attn_kernel(
    const float* __restrict__ qkv, float* __restrict__ ctx)
{
    extern __shared__ float sm[];
    float* sQ  = sm + SM_Q;
    float* sK  = sm + SM_K;
    float* sV  = sm + SM_V;
    float* sP  = sm + SM_P;
    float* sPV = sm + SM_PV;

    const int tid = threadIdx.x;
    const int qt = (int)gridDim.x - 1 - (int)blockIdx.x;  // heavy tiles first
    const int h  = blockIdx.y;
    const int b  = blockIdx.z;
    const int q0 = qt * AT;

    const int rq = tid >> 4;            // 0..15 (softmax row group)
    const int cq = tid & 15;            // 0..15 (softmax col group)

    const int wid = tid >> 5;           // 0..7
    const int wm2 = wid >> 1;           // 0..3 -> S rows 16*wm2
    const int wn2 = wid & 1;            // 0..1 -> S cols 32*wn2

    const size_t rs = 3 * D_;
    const float* baseQ = qkv + (size_t)(b * S_) * rs + h * HD;
    const float* baseK = baseQ + D_;
    const float* baseV = baseQ + 2 * D_;

    // Per-thread load coords: e = tid + 256*p -> row e>>4, col (e&15)*4
    int lc[4], ld4[4];
    #pragma unroll
    for (int p = 0; p < 4; p++) {
        int e = tid + (p << 8);
        lc[p]  = e >> 4;
        ld4[p] = (e & 15) << 2;
    }

    // Load Q tile [r][d] with QSCALE (STS.128)
    #pragma unroll
    for (int p = 0; p < 4; p++) {
        int r = lc[p], d4 = ld4[p];
        float4 q4 = *(const float4*)(baseQ + (size_t)(q0 + r) * rs + d4);
        q4.x *= QSCALE; q4.y *= QSCALE; q4.z *= QSCALE; q4.w *= QSCALE;
        *(float4*)&sQ[r * KLD + d4] = q4;
    }

    float m[4], l[4], o[4][4];
    #pragma unroll
    for (int i = 0; i < 4; i++) {
        m[i] = -CUDART_INF_F; l[i] = 0.f;
        #pragma unroll
        for (int j = 0; j < 4; j++) o[i][j] = 0.f;
    }

    for (int kt = 0; kt <= qt; kt++) {
        const int k0 = kt * AT;

        // Batched global loads (MLP=8)
        float4 kv4[4], vv4[4];
        #pragma unroll
        for (int p = 0; p < 4; p++) {
            const size_t roff = (size_t)(k0 + lc[p]) * rs + ld4[p];
            kv4[p] = *(const float4*)(baseK + roff);
            vv4[p] = *(const float4*)(baseV + roff);
        }

        __syncthreads();   // prior tile fully consumed (sK/sV readers done)
        #pragma unroll
        for (int p = 0; p < 4; p++) {
            int c = lc[p], d4 = ld4[p];
            *(float4*)&sK[c * KLD + d4] = kv4[p];
            *(float4*)&sV[c * KLD + d4] = vv4[p];
        }
        __syncthreads();

        // ---- S = Q @ K^T on tensor cores (each warp: 16x32 patch) ----
        {
            wmma::fragment<wmma::accumulator, 16, 16, 8, float> sacc[2];
            #pragma unroll
            for (int j = 0; j < 2; j++) wmma::fill_fragment(sacc[j], 0.f);
            #pragma unroll
            for (int kd = 0; kd < 8; kd++) {
                wmma::fragment<wmma::matrix_a, 16, 16, 8, wmma::precision::tf32,
                               wmma::row_major> af;
                wmma::fragment<wmma::matrix_b, 16, 16, 8, wmma::precision::tf32,
                               wmma::col_major> bf[2];
                wmma::load_matrix_sync(af, &sQ[(wm2 * 16) * KLD + kd * 8], KLD);
                #pragma unroll
                for (int j = 0; j < 2; j++)
                    wmma::load_matrix_sync(bf[j],
                        &sK[(wn2 * 32 + j * 16) * KLD + kd * 8], KLD);
                #pragma unroll
                for (int j = 0; j < 2; j++)
                    wmma::mma_sync(sacc[j], af, bf[j], sacc[j]);
            }
            #pragma unroll
            for (int j = 0; j < 2; j++)
                wmma::store_matrix_sync(
                    &sP[(wm2 * 16) * PLD + wn2 * 32 + j * 16],
                    sacc[j], PLD, wmma::mem_row_major);
        }
        __syncthreads();   // S visible to softmax threads

        // ---- scalar online softmax (verified skeleton; scores from sP) ----
        float acc[4][4];
        #pragma unroll
        for (int i = 0; i < 4; i++) {
            float4 s4 = *(float4*)&sP[((rq << 2) + i) * PLD + (cq << 2)];
            acc[i][0] = s4.x; acc[i][1] = s4.y; acc[i][2] = s4.z; acc[i][3] = s4.w;
        }

        if (kt == qt) {
            #pragma unroll
            for (int i = 0; i < 4; i++)
                #pragma unroll
                for (int j = 0; j < 4; j++)
                    if (k0 + (cq << 2) + j > q0 + (rq << 2) + i)
                        acc[i][j] = -FLT_MAX;
        }

        float p[4][4], alpha[4], mnew[4], ssum[4];
        #pragma unroll
        for (int i = 0; i < 4; i++)
            mnew[i] = fmaxf(fmaxf(acc[i][0], acc[i][1]),
                            fmaxf(acc[i][2], acc[i][3]));
        #pragma unroll
        for (int off = 8; off >= 1; off >>= 1) {
            #pragma unroll
            for (int i = 0; i < 4; i++)
                mnew[i] = fmaxf(mnew[i],
                                __shfl_xor_sync(0xffffffffu, mnew[i], off));
        }
        #pragma unroll
        for (int i = 0; i < 4; i++) mnew[i] = fmaxf(m[i], mnew[i]);

        #pragma unroll
        for (int i = 0; i < 4; i++) {
            p[i][0] = ex2f(acc[i][0] - mnew[i]);
            p[i][1] = ex2f(acc[i][1] - mnew[i]);
            p[i][2] = ex2f(acc[i][2] - mnew[i]);
            p[i][3] = ex2f(acc[i][3] - mnew[i]);
            ssum[i] = (p[i][0] + p[i][1]) + (p[i][2] + p[i][3]);
        }
        #pragma unroll
        for (int off = 8; off >= 1; off >>= 1) {
            #pragma unroll
            for (int i = 0; i < 4; i++)
                ssum[i] += __shfl_xor_sync(0xffffffffu, ssum[i], off);
        }
        #pragma unroll
        for (int i = 0; i < 4; i++) {
            alpha[i] = ex2f(m[i] - mnew[i]);
            m[i] = mnew[i];
            l[i] = l[i] * alpha[i] + ssum[i];
        }

        // Write P back; rescale o
        #pragma unroll
        for (int i = 0; i < 4; i++)
            *(float4*)&sP[((rq << 2) + i) * PLD + (cq << 2)] =
                make_float4(p[i][0], p[i][1], p[i][2], p[i][3]);
        #pragma unroll
        for (int i = 0; i < 4; i++)
            #pragma unroll
            for (int j = 0; j < 4; j++) o[i][j] *= alpha[i];
        __syncthreads();   // P complete before PV mma reads it

        // ---- PV = P @ V on tensor cores (each warp: 16x32 patch) ----
        {
            wmma::fragment<wmma::accumulator, 16, 16, 8, float> pacc[2];
            #pragma unroll
            for (int j = 0; j < 2; j++) wmma::fill_fragment(pacc[j], 0.f);
            #pragma unroll
            for (int kc = 0; kc < 8; kc++) {
                wmma::fragment<wmma::matrix_a, 16, 16, 8, wmma::precision::tf32,
                               wmma::row_major> af;
                wmma::fragment<wmma::matrix_b, 16, 16, 8, wmma::precision::tf32,
                               wmma::row_major> bf[2];
                wmma::load_matrix_sync(af, &sP[(wm2 * 16) * PLD + kc * 8], PLD);
                #pragma unroll
                for (int j = 0; j < 2; j++)
                    wmma::load_matrix_sync(bf[j],
                        &sV[(kc * 8) * KLD + wn2 * 32 + j * 16], KLD);
                #pragma unroll
                for (int j = 0; j < 2; j++)
                    wmma::mma_sync(pacc[j], af, bf[j], pacc[j]);
            }
            #pragma unroll
            for (int j = 0; j < 2; j++)
                wmma::store_matrix_sync(
                    &sPV[(wm2 * 16) * PLD + wn2 * 32 + j * 16],
                    pacc[j], PLD, wmma::mem_row_major);
        }
        __syncthreads();   // PV visible to accumulation threads

        // o += PV (alpha already applied)
        #pragma unroll
        for (int i = 0; i < 4; i++) {
            float4 v4 = *(float4*)&sPV[((rq << 2) + i) * PLD + (cq << 2)];
            o[i][0] += v4.x; o[i][1] += v4.y; o[i][2] += v4.z; o[i][3] += v4.w;
        }
    }

    // Final normalize + write ctx
    #pragma unroll
    for (int i = 0; i < 4; i++) {
        float inv = 1.f / l[i];
        float4 ov = make_float4(o[i][0] * inv, o[i][1] * inv,
                                o[i][2] * inv, o[i][3] * inv);
        *(float4*)(ctx + (size_t)(b * S_ + q0 + (rq << 2) + i) * D_
                   + h * HD + (cq << 2)) = ov;
    }
}

// ---------------------------------------------------------------------------
extern "C" void kernel_launch(void* const* d_in, const int* in_sizes, int n_in,
                              void* d_out, int out_size)
{
    const float* hs    = (const float*)d_in[0];
    const float* att_w = (const float*)d_in[1];
    const float* att_b = (const float*)d_in[2];
    const float* out_w = (const float*)d_in[3];
    const float* out_b = (const float*)d_in[4];
    float* out = (float*)d_out;

    void *qkvp = nullptr, *ctxp = nullptr;
    cudaGetSymbolAddress(&qkvp, g_qkv);
    cudaGetSymbolAddress(&ctxp, g_ctx);

    // 0) Prefill C buffers with broadcast biases
    prefill_bias_kernel<<<(QKV4 + OUT4 + 255) / 256, 256>>>(
        (float*)qkvp, att_b, out, out_b);

    // 1) QKV projection (tf32 tensor cores)
    gemm_tf32_kernel<<<dim3(3 * D_ / TBN, B_ * S_ / TBM), 256>>>(
        hs, att_w, (float*)qkvp, B_ * S_, 3 * D_, D_);

    // 2) Causal flash attention, tensor-core QK^T + PV
    cudaFuncSetAttribute(attn_kernel,
                         cudaFuncAttributeMaxDynamicSharedMemorySize, ATTN_SMEM);
    attn_kernel<<<dim3(S_ / AT, H_, B_), 256, ATTN_SMEM>>>(
        (const float*)qkvp, (float*)ctxp);

    // 3) Output projection (tf32 tensor cores)
    gemm_tf32_kernel<<<dim3(D_ / TBN, B_ * S_ / TBM), 256>>>(
        (const float*)ctxp, out_w, out, B_ * S_, D_, D_);
}